// round 12
// baseline (speedup 1.0000x reference)
#include <cuda_runtime.h>
#include <cuda_fp16.h>
#include <cstdint>

// Shapes fixed by the reference.
#define BB 512     // batch
#define HH 1024    // hidden
#define II 256     // input / output feature
#define LL 256     // rollout length
#define G3 3072    // 3*HH
#define NG 4096    // gate GEMM output width (4*HH)
#define N5 4352    // NG + II (appended W_head rows -> y)
#define KK 1024    // GEMM K
#define NCTAS 272  // 4 m-rows x 68 n-tiles (128x64) -> 2 CTAs/SM
#define GROUP 68   // CTAs per independent m-row group
#define TPB 128

#define KC 128                   // fp16 K elements per chunk (256 bytes/row)
#define NCHUNK (KK / KC)         // 8
#define ROWB 272                 // padded smem row bytes (256 + 16)
#define BUFA (128 * ROWB)        // 34816 B: 128x128 fp16 A tile
#define BUFB (64 * ROWB)         // 17408 B: 64x128 fp16 B tile
#define STAGE_BYTES (BUFA + BUFB)
#define NSTG 2
#define SMEM_DYN (NSTG * STAGE_BYTES)   // 104448 B -> 2 CTAs/SM fit

typedef __half fp16;

// ---------------------------------------------------------------------------
// Static device scratch.
// ---------------------------------------------------------------------------
__device__ fp16  g_hb[2 * BB * HH];     // double-buffered fp16 hidden state
__device__ fp16  g_Wf[N5 * KK];         // fp16 weights, 16j-interleaved
__device__ fp16  g_W0f[N5 * KK];        // fp16 step-0 weights, interleaved
__device__ float g_b5[NG];              // biases (gate-major layout)
__device__ float g_b50[NG];
__device__ unsigned g_bar4[4 * 32];     // per-m-row barrier counters

// ---------------------------------------------------------------------------
// PTX helpers (base ISA, valid on compute_103)
// ---------------------------------------------------------------------------
__device__ __forceinline__ uint32_t smem_u32(const void* p) {
    uint32_t a;
    asm("{ .reg .u64 t; cvta.to.shared.u64 t, %1; cvt.u32.u64 %0, t; }" : "=r"(a) : "l"(p));
    return a;
}
__device__ __forceinline__ void ldsm_x4(uint32_t* r, uint32_t addr) {
    asm volatile("ldmatrix.sync.aligned.m8n8.x4.shared.b16 {%0,%1,%2,%3}, [%4];"
                 : "=r"(r[0]), "=r"(r[1]), "=r"(r[2]), "=r"(r[3]) : "r"(addr));
}
__device__ __forceinline__ void mma_fp16(float* d, const uint32_t* a,
                                         uint32_t b0, uint32_t b1) {
    asm volatile(
        "mma.sync.aligned.m16n8k16.row.col.f32.f16.f16.f32 "
        "{%0,%1,%2,%3}, {%4,%5,%6,%7}, {%8,%9}, {%0,%1,%2,%3};"
        : "+f"(d[0]), "+f"(d[1]), "+f"(d[2]), "+f"(d[3])
        : "r"(a[0]), "r"(a[1]), "r"(a[2]), "r"(a[3]), "r"(b0), "r"(b1));
}
#define CP_ASYNC16(smem, gptr) \
    asm volatile("cp.async.cg.shared.global [%0], [%1], 16;" :: "r"(smem), "l"(gptr))
#define CP_COMMIT() asm volatile("cp.async.commit_group;" ::: "memory")
template <int N>
__device__ __forceinline__ void cp_wait() {
    asm volatile("cp.async.wait_group %0;" :: "n"(N) : "memory");
}
__device__ __forceinline__ float fsigmoid(float x) {
    return __fdividef(1.0f, 1.0f + __expf(-x));
}
__device__ __forceinline__ float ftanh(float x) {
    float e = __expf(2.0f * x);
    return 1.0f - __fdividef(2.0f, e + 1.0f);
}
// Interleaved row for gate row (g, j): (j/16)*64 + g*16 + (j%16)
__device__ __forceinline__ int irow(int g, int j) {
    return ((j >> 4) << 6) + (g << 4) + (j & 15);
}

// ---------------------------------------------------------------------------
// Fused setup: h0 (buffer 0), barrier counters, biases, static weight rows.
// ---------------------------------------------------------------------------
__global__ void setup_all(const float* __restrict__ ctx,
                          const float* __restrict__ Wih,
                          const float* __restrict__ bih,
                          const float* __restrict__ bhh,
                          const float* __restrict__ bhead,
                          const float* __restrict__ Whh,
                          const float* __restrict__ Whead) {
    const int gs = gridDim.x * blockDim.x;
    const int t0 = blockIdx.x * blockDim.x + threadIdx.x;

    for (int i = t0; i < BB * HH; i += gs) g_hb[i] = __float2half(ctx[i]);
    for (int i = t0; i < 4 * 32; i += gs) g_bar4[i] = 0u;

    for (int j = t0; j < NG; j += gs) {
        float v0, v1;
        if (j < 2048)      v0 = bih[j] + bhh[j];
        else if (j < G3)   v0 = bih[j];
        else               v0 = bhh[j - 1024];
        if (j < G3) {
            float d = 0.0f;
            const float* wr = Wih + (size_t)j * II;
            for (int i = 0; i < II; ++i) d += wr[i] * bhead[i];
            float bc = bih[j] + d;
            v1 = (j < 2048) ? (bhh[j] + bc) : bc;
        } else {
            v1 = bhh[j - 1024];
        }
        g_b50[j] = v0;
        g_b5[j]  = v1;
    }

    // Rows n in [3072, 4352): ghn block (Whh_n) and y block (Whead).
    for (int idx = t0; idx < (N5 - G3) * KK; idx += gs) {
        int o = G3 + (idx >> 10);
        int k = idx & 1023;
        int nrow;
        float v;
        if (o < NG) {
            nrow = irow(3, o - G3);
            v = Whh[(size_t)(o - 1024) * KK + k];
        } else {
            nrow = o;
            v = Whead[(size_t)(o - NG) * KK + k];
        }
        fp16 h = __float2half(v);
        g_Wf[(size_t)nrow * KK + k]  = h;
        g_W0f[(size_t)nrow * KK + k] = h;
    }
}

// Wc = W_ih @ W_head for rows n < 3072; writes fp16 interleaved weights.
__global__ void __launch_bounds__(256)
wc_gemm(const float* __restrict__ Wih,
        const float* __restrict__ Whh,
        const float* __restrict__ Whead) {
    __shared__ __align__(16) float As[16][68];
    __shared__ __align__(16) float Bs[16][68];
    const int tid = threadIdx.x;
    const int n0 = blockIdx.y * 64;
    const int k0 = blockIdx.x * 64;
    const int ty = tid >> 4, tx = tid & 15;

    float acc[4][4] = {};
    for (int i0 = 0; i0 < II; i0 += 16) {
        {
            int row = tid >> 2, ic = (tid & 3) * 4;
            float4 av = *reinterpret_cast<const float4*>(Wih + (size_t)(n0 + row) * II + i0 + ic);
            As[ic + 0][row] = av.x; As[ic + 1][row] = av.y;
            As[ic + 2][row] = av.z; As[ic + 3][row] = av.w;
        }
        {
            int r = tid >> 4, kc = (tid & 15) * 4;
            float4 bv = *reinterpret_cast<const float4*>(Whead + (size_t)(i0 + r) * KK + k0 + kc);
            *reinterpret_cast<float4*>(&Bs[r][kc]) = bv;
        }
        __syncthreads();
#pragma unroll
        for (int i = 0; i < 16; ++i) {
            float a[4], b[4];
#pragma unroll
            for (int u = 0; u < 4; ++u) a[u] = As[i][ty * 4 + u];
#pragma unroll
            for (int u = 0; u < 4; ++u) b[u] = Bs[i][tx * 4 + u];
#pragma unroll
            for (int r = 0; r < 4; ++r)
#pragma unroll
                for (int c = 0; c < 4; ++c) acc[r][c] = fmaf(a[r], b[c], acc[r][c]);
        }
        __syncthreads();
    }
#pragma unroll
    for (int r = 0; r < 4; ++r) {
        int n = n0 + ty * 4 + r;
        size_t nr = (size_t)irow(n >> 10, n & 1023) * KK;
#pragma unroll
        for (int c = 0; c < 4; ++c) {
            int k = k0 + tx * 4 + c;
            float base = (n < 2048) ? Whh[(size_t)n * KK + k] : 0.0f;
            g_Wf[nr + k]  = __float2half(acc[r][c] + base);
            g_W0f[nr + k] = __float2half(base);
        }
    }
}

// ---------------------------------------------------------------------------
// Per-m-row barrier: 68 CTAs of one m-row group.
// ---------------------------------------------------------------------------
__device__ __forceinline__ void row_barrier(int mrow, unsigned& phase) {
    __threadfence();
    __syncthreads();
    phase += GROUP;
    if (threadIdx.x == 0) {
        atomicAdd(&g_bar4[mrow * 32], 1u);
        while (*(volatile unsigned*)&g_bar4[mrow * 32] < phase) { }
        __threadfence();
    }
    __syncthreads();
}

// ---------------------------------------------------------------------------
// Persistent rollout, 128x64 tiles, 2 CTAs/SM.
// 4 warps, each 32 rows x 64 cols (same microkernel as before).
// Gate tile nt<64 covers j block [16nt,16nt+16) x 4 gates (16j interleave).
// y tiles nt 64..67. Double-buffered h (read t&1, write (t+1)&1).
// Safe 2-stage pipeline: wait -> sync -> compute -> sync -> load(c+2).
// ---------------------------------------------------------------------------
__global__ void __launch_bounds__(TPB, 2)
rollout(float* __restrict__ out, const float* __restrict__ ctx,
        const float* __restrict__ b_head) {
    extern __shared__ __align__(128) char smem[];
    __shared__ float s_b5[64], s_b50[64];
    const uint32_t sm0 = smem_u32(smem);

    const int tid = threadIdx.x;
    const int lane = tid & 31;
    const int wm = tid >> 5;             // warp = m-group: rows 32*wm .. +31
    const int cta = blockIdx.x;
    const int mrow = cta & 3;
    const int m0 = mrow * 128;
    const int nt = cta >> 2;             // 0..67
    const bool is_y = (nt >= 64);

    // Per-CTA bias staging. Gate tile col c = 16*g + jl, j = 16*nt + jl.
    if (tid < 64) {
        if (!is_y) {
            int g = tid >> 4, jl = tid & 15;
            s_b5[tid]  = g_b5[g * 1024 + 16 * nt + jl];
            s_b50[tid] = g_b50[g * 1024 + 16 * nt + jl];
        } else {
            s_b5[tid] = __ldg(b_head + (nt - 64) * 64 + tid);
        }
    }
    __syncthreads();

    const int jc = 2 * (lane & 3);
    const int rq = lane >> 2;

    // Register-resident fp32 h_old: [mt][rs][fh][e] -> 16 values.
    float ho[16];
    if (!is_y) {
#pragma unroll
        for (int mt = 0; mt < 2; ++mt)
#pragma unroll
            for (int rs = 0; rs < 2; ++rs)
#pragma unroll
                for (int fh = 0; fh < 2; ++fh)
#pragma unroll
                    for (int e = 0; e < 2; ++e) {
                        int row = m0 + 32 * wm + 16 * mt + 8 * rs + rq;
                        int j = 16 * nt + 8 * fh + jc + e;
                        ho[((mt * 2 + rs) * 2 + fh) * 2 + e] =
                            ctx[(size_t)row * HH + j];
                    }
    }

    const uint32_t lm = (uint32_t)(lane & 15) * ROWB + (uint32_t)(lane >> 4) * 16;

    // Loaders. A: 2048 16B segs (16/thread); B: 1024 (8/thread).
    auto load_B = [&](const fp16* Bw, int kc0, int sbuf) {
        const uint32_t sb = sm0 + sbuf * STAGE_BYTES + BUFA;
#pragma unroll
        for (int p = 0; p < 8; ++p) {
            const int s = tid + TPB * p;
            const int row = s >> 4;
            const int cs = s & 15;
            CP_ASYNC16(sb + (uint32_t)row * ROWB + (uint32_t)cs * 16,
                       Bw + (size_t)row * KK + kc0 + cs * 8);
        }
        CP_COMMIT();
    };
    auto load_A = [&](const fp16* Am, int kc0, int sbuf) {
        const uint32_t sb = sm0 + sbuf * STAGE_BYTES;
#pragma unroll
        for (int p = 0; p < 16; ++p) {
            const int s = tid + TPB * p;
            const int row = s >> 4;
            const int cs = s & 15;
            CP_ASYNC16(sb + (uint32_t)row * ROWB + (uint32_t)cs * 16,
                       Am + (size_t)row * KK + kc0 + cs * 8);
        }
        CP_COMMIT();
    };
    auto load_AB = [&](const fp16* Am, const fp16* Bw, int kc0, int sbuf) {
        const uint32_t sa = sm0 + sbuf * STAGE_BYTES;
#pragma unroll
        for (int p = 0; p < 16; ++p) {
            const int s = tid + TPB * p;
            const int row = s >> 4;
            const int cs = s & 15;
            CP_ASYNC16(sa + (uint32_t)row * ROWB + (uint32_t)cs * 16,
                       Am + (size_t)row * KK + kc0 + cs * 8);
            if (p < 8)
                CP_ASYNC16(sa + BUFA + (uint32_t)row * ROWB + (uint32_t)cs * 16,
                           Bw + (size_t)row * KK + kc0 + cs * 8);
        }
        CP_COMMIT();
    };

    unsigned gphase = 0;

    // Pre-loop B prefetch for t=0 (gate CTAs active at t=0).
    if (!is_y) load_B(g_W0f + (size_t)(nt * 64) * KK, 0, 0);

    for (int t = 0; t <= LL; ++t) {
        const bool active = (t < LL) ? !(t == 0 && is_y) : is_y;
        if (active) {
            const fp16* Bw = ((t == 0) ? g_W0f : g_Wf) + (size_t)(nt * 64) * KK;
            const fp16* Am = g_hb + (size_t)(t & 1) * (BB * HH) + (size_t)m0 * KK;

            float acc[2][8][4];
#pragma unroll
            for (int i = 0; i < 2; ++i)
#pragma unroll
                for (int j = 0; j < 8; ++j)
#pragma unroll
                    for (int k = 0; k < 4; ++k) acc[i][j][k] = 0.0f;

            // Prologue: A chunk 0 (B0 pre-barrier), then chunk 1 full.
            load_A(Am, 0, 0);
            load_AB(Am, Bw, KC, 1);

            for (int c = 0; c < NCHUNK; ++c) {
                const int sbuf = c & 1;
                if (c + 1 < NCHUNK) cp_wait<1>(); else cp_wait<0>();
                __syncthreads();

                const uint32_t sb = sm0 + sbuf * STAGE_BYTES;
                const uint32_t abase = sb + (uint32_t)(32 * wm) * ROWB + lm;
                const uint32_t bbase = sb + BUFA + lm;
#pragma unroll
                for (int ks = 0; ks < 8; ++ks) {
                    const uint32_t ko = (uint32_t)ks * 32;
                    uint32_t ah0[4], ah1[4];
                    ldsm_x4(ah0, abase + ko);
                    ldsm_x4(ah1, abase + (uint32_t)(16 * ROWB) + ko);
#pragma unroll
                    for (int u = 0; u < 4; ++u) {
                        uint32_t bb[4];
                        ldsm_x4(bb, bbase + (uint32_t)(16 * u) * ROWB + ko);
                        mma_fp16(acc[0][2 * u + 0], ah0, bb[0], bb[2]);
                        mma_fp16(acc[0][2 * u + 1], ah0, bb[1], bb[3]);
                        mma_fp16(acc[1][2 * u + 0], ah1, bb[0], bb[2]);
                        mma_fp16(acc[1][2 * u + 1], ah1, bb[1], bb[3]);
                    }
                }
                // Reload this stage with chunk c+2 (safe: sync after compute).
                if (c + 2 < NCHUNK) {
                    __syncthreads();
                    load_AB(Am, Bw, (c + 2) * KC, sbuf);
                }
            }

            // ---- fused epilogue ----
            if (!is_y) {
                fp16* hw = g_hb + (size_t)((t + 1) & 1) * (BB * HH);
                const float* sb2 = (t == 0) ? s_b50 : s_b5;
#pragma unroll
                for (int mt = 0; mt < 2; ++mt)
#pragma unroll
                    for (int rs = 0; rs < 2; ++rs) {
                        const int row = m0 + 32 * wm + 16 * mt + 8 * rs + rq;
#pragma unroll
                        for (int fh = 0; fh < 2; ++fh) {
                            float hn[2];
#pragma unroll
                            for (int e = 0; e < 2; ++e) {
                                const int cb = 8 * fh + jc + e;   // jl
                                float rp = acc[mt][0 + fh][2 * rs + e] + sb2[cb];
                                float zp = acc[mt][2 + fh][2 * rs + e] + sb2[cb + 16];
                                float gn = acc[mt][4 + fh][2 * rs + e] + sb2[cb + 32];
                                float gh = acc[mt][6 + fh][2 * rs + e] + sb2[cb + 48];
                                float r = fsigmoid(rp);
                                float z = fsigmoid(zp);
                                float nn = ftanh(gn + r * gh);
                                const int ii = ((mt * 2 + rs) * 2 + fh) * 2 + e;
                                float hnew = (1.0f - z) * nn + z * ho[ii];
                                ho[ii] = hnew;
                                hn[e] = hnew;
                            }
                            const int jb = 16 * nt + 8 * fh + jc;
                            *reinterpret_cast<__half2*>(hw + (size_t)row * HH + jb) =
                                __floats2half2_rn(hn[0], hn[1]);
                        }
                    }
            } else {
                float* yb = out + (size_t)(t - 1) * BB * II;
#pragma unroll
                for (int mt = 0; mt < 2; ++mt)
#pragma unroll
                    for (int rs = 0; rs < 2; ++rs) {
                        const int row = m0 + 32 * wm + 16 * mt + 8 * rs + rq;
#pragma unroll
                        for (int f = 0; f < 8; ++f) {
                            const int ci = 8 * f + jc;            // col in tile
                            const int col = (nt - 64) * 64 + ci;
                            float2 v = make_float2(acc[mt][f][2 * rs + 0] + s_b5[ci],
                                                   acc[mt][f][2 * rs + 1] + s_b5[ci + 1]);
                            *reinterpret_cast<float2*>(yb + (size_t)row * II + col) = v;
                        }
                    }
            }
        }

        if (t == LL) break;

        // Pre-barrier B prefetch for t+1 (weights static; stage 0's B half
        // was last consumed at chunk 6). Gate CTAs inactive at t+1 == LL.
        const bool next_active = is_y ? true : (t + 1 < LL);
        if (next_active) load_B(g_Wf + (size_t)(nt * 64) * KK, 0, 0);

        row_barrier(mrow, gphase);
    }
}

// ---------------------------------------------------------------------------
// 3 graph nodes: setup_all, wc_gemm, rollout.
// ---------------------------------------------------------------------------
extern "C" void kernel_launch(void* const* d_in, const int* in_sizes, int n_in,
                              void* d_out, int out_size) {
    const float *ctx = nullptr, *Wih = nullptr, *Whh = nullptr,
                *bih = nullptr, *bhh = nullptr, *Whead = nullptr, *bhead = nullptr;
    int b3_seen = 0;
    for (int i = 0; i < n_in; i++) {
        long sz = in_sizes[i];
        const float* p = (const float*)d_in[i];
        if (sz == (long)BB * HH) ctx = p;
        else if (sz == (long)G3 * II) Wih = p;
        else if (sz == (long)G3 * HH) Whh = p;
        else if (sz == (long)G3) { if (b3_seen++ == 0) bih = p; else bhh = p; }
        else if (sz == (long)II * HH) Whead = p;
        else if (sz == (long)II) bhead = p;
    }
    float* out = (float*)d_out;

    cudaFuncSetAttribute(rollout, cudaFuncAttributeMaxDynamicSharedMemorySize, SMEM_DYN);

    setup_all<<<640, 256>>>(ctx, Wih, bih, bhh, bhead, Whh, Whead);
    wc_gemm<<<dim3(KK / 64, G3 / 64), 256>>>(Wih, Whh, Whead);
    rollout<<<NCTAS, TPB, SMEM_DYN>>>(out, ctx, bhead);

    (void)out_size;
    (void)n_in;
}

// round 13
// speedup vs baseline: 1.0254x; 1.0254x over previous
#include <cuda_runtime.h>
#include <cuda_fp16.h>
#include <cstdint>

// Shapes fixed by the reference.
#define BB 512     // batch
#define HH 1024    // hidden
#define II 256     // input / output feature
#define LL 256     // rollout length
#define G3 3072    // 3*HH
#define NG 4096    // gate GEMM output width (4*HH)
#define N5 4352    // NG + II (appended W_head rows -> y)
#define KK 1024    // GEMM K
#define NCTAS 136  // 4 m-rows x 34 n-tiles (128x128)
#define GROUP 34   // CTAs per independent m-row group
#define TPB 256

#define KC 128                   // fp16 K elements per chunk (256 bytes/row)
#define NCHUNK (KK / KC)         // 8
#define ROWB 272                 // padded smem row bytes (256 + 16)
#define BUFB (128 * ROWB)        // 34816 B per 128x128 fp16 tile
#define STAGE_BYTES (2 * BUFB)   // A, B
#define NSTG 3
#define SMEM_DYN (NSTG * STAGE_BYTES)   // 208896 B (< 227 KB limit)

typedef __half fp16;

// ---------------------------------------------------------------------------
// Static device scratch.
// ---------------------------------------------------------------------------
__device__ fp16  g_hb[2 * BB * HH];     // DOUBLE-buffered fp16 hidden state
__device__ fp16  g_Wf[N5 * KK];         // fp16 weights, 16j-interleaved
__device__ fp16  g_W0f[N5 * KK];        // fp16 step-0 weights, interleaved
__device__ float g_b5[NG];              // biases (gate-major layout)
__device__ float g_b50[NG];
__device__ unsigned g_bar4[4 * 32];     // per-m-row barrier counters

// ---------------------------------------------------------------------------
// PTX helpers (base ISA, valid on compute_103)
// ---------------------------------------------------------------------------
__device__ __forceinline__ uint32_t smem_u32(const void* p) {
    uint32_t a;
    asm("{ .reg .u64 t; cvta.to.shared.u64 t, %1; cvt.u32.u64 %0, t; }" : "=r"(a) : "l"(p));
    return a;
}
__device__ __forceinline__ void ldsm_x4(uint32_t* r, uint32_t addr) {
    asm volatile("ldmatrix.sync.aligned.m8n8.x4.shared.b16 {%0,%1,%2,%3}, [%4];"
                 : "=r"(r[0]), "=r"(r[1]), "=r"(r[2]), "=r"(r[3]) : "r"(addr));
}
__device__ __forceinline__ void mma_fp16(float* d, const uint32_t* a,
                                         uint32_t b0, uint32_t b1) {
    asm volatile(
        "mma.sync.aligned.m16n8k16.row.col.f32.f16.f16.f32 "
        "{%0,%1,%2,%3}, {%4,%5,%6,%7}, {%8,%9}, {%0,%1,%2,%3};"
        : "+f"(d[0]), "+f"(d[1]), "+f"(d[2]), "+f"(d[3])
        : "r"(a[0]), "r"(a[1]), "r"(a[2]), "r"(a[3]), "r"(b0), "r"(b1));
}
#define CP_ASYNC16(smem, gptr) \
    asm volatile("cp.async.cg.shared.global [%0], [%1], 16;" :: "r"(smem), "l"(gptr))
#define CP_COMMIT() asm volatile("cp.async.commit_group;" ::: "memory")
template <int N>
__device__ __forceinline__ void cp_wait() {
    asm volatile("cp.async.wait_group %0;" :: "n"(N) : "memory");
}
__device__ __forceinline__ float fsigmoid(float x) {
    return __fdividef(1.0f, 1.0f + __expf(-x));
}
__device__ __forceinline__ float ftanh(float x) {
    float e = __expf(2.0f * x);
    return 1.0f - __fdividef(2.0f, e + 1.0f);
}
// Interleaved row for gate row (g, j): (j/16)*64 + g*16 + (j%16)
__device__ __forceinline__ int irow(int g, int j) {
    return ((j >> 4) << 6) + (g << 4) + (j & 15);
}

// ---------------------------------------------------------------------------
// Fused setup: h0 (buffer 0), barrier counters, biases, static weight rows.
// ---------------------------------------------------------------------------
__global__ void setup_all(const float* __restrict__ ctx,
                          const float* __restrict__ Wih,
                          const float* __restrict__ bih,
                          const float* __restrict__ bhh,
                          const float* __restrict__ bhead,
                          const float* __restrict__ Whh,
                          const float* __restrict__ Whead) {
    const int gs = gridDim.x * blockDim.x;
    const int t0 = blockIdx.x * blockDim.x + threadIdx.x;

    for (int i = t0; i < BB * HH; i += gs) g_hb[i] = __float2half(ctx[i]);
    for (int i = t0; i < 4 * 32; i += gs) g_bar4[i] = 0u;

    for (int j = t0; j < NG; j += gs) {
        float v0, v1;
        if (j < 2048)      v0 = bih[j] + bhh[j];
        else if (j < G3)   v0 = bih[j];
        else               v0 = bhh[j - 1024];
        if (j < G3) {
            float d = 0.0f;
            const float* wr = Wih + (size_t)j * II;
            for (int i = 0; i < II; ++i) d += wr[i] * bhead[i];
            float bc = bih[j] + d;
            v1 = (j < 2048) ? (bhh[j] + bc) : bc;
        } else {
            v1 = bhh[j - 1024];
        }
        g_b50[j] = v0;
        g_b5[j]  = v1;
    }

    // Rows n in [3072, 4352): ghn block (Whh_n) and y block (Whead).
    for (int idx = t0; idx < (N5 - G3) * KK; idx += gs) {
        int o = G3 + (idx >> 10);
        int k = idx & 1023;
        int nrow;
        float v;
        if (o < NG) {
            nrow = irow(3, o - G3);
            v = Whh[(size_t)(o - 1024) * KK + k];
        } else {
            nrow = o;
            v = Whead[(size_t)(o - NG) * KK + k];
        }
        fp16 h = __float2half(v);
        g_Wf[(size_t)nrow * KK + k]  = h;
        g_W0f[(size_t)nrow * KK + k] = h;
    }
}

// Wc = W_ih @ W_head for rows n < 3072; writes fp16 interleaved weights.
__global__ void __launch_bounds__(256)
wc_gemm(const float* __restrict__ Wih,
        const float* __restrict__ Whh,
        const float* __restrict__ Whead) {
    __shared__ __align__(16) float As[16][68];
    __shared__ __align__(16) float Bs[16][68];
    const int tid = threadIdx.x;
    const int n0 = blockIdx.y * 64;
    const int k0 = blockIdx.x * 64;
    const int ty = tid >> 4, tx = tid & 15;

    float acc[4][4] = {};
    for (int i0 = 0; i0 < II; i0 += 16) {
        {
            int row = tid >> 2, ic = (tid & 3) * 4;
            float4 av = *reinterpret_cast<const float4*>(Wih + (size_t)(n0 + row) * II + i0 + ic);
            As[ic + 0][row] = av.x; As[ic + 1][row] = av.y;
            As[ic + 2][row] = av.z; As[ic + 3][row] = av.w;
        }
        {
            int r = tid >> 4, kc = (tid & 15) * 4;
            float4 bv = *reinterpret_cast<const float4*>(Whead + (size_t)(i0 + r) * KK + k0 + kc);
            *reinterpret_cast<float4*>(&Bs[r][kc]) = bv;
        }
        __syncthreads();
#pragma unroll
        for (int i = 0; i < 16; ++i) {
            float a[4], b[4];
#pragma unroll
            for (int u = 0; u < 4; ++u) a[u] = As[i][ty * 4 + u];
#pragma unroll
            for (int u = 0; u < 4; ++u) b[u] = Bs[i][tx * 4 + u];
#pragma unroll
            for (int r = 0; r < 4; ++r)
#pragma unroll
                for (int c = 0; c < 4; ++c) acc[r][c] = fmaf(a[r], b[c], acc[r][c]);
        }
        __syncthreads();
    }
#pragma unroll
    for (int r = 0; r < 4; ++r) {
        int n = n0 + ty * 4 + r;
        size_t nr = (size_t)irow(n >> 10, n & 1023) * KK;
#pragma unroll
        for (int c = 0; c < 4; ++c) {
            int k = k0 + tx * 4 + c;
            float base = (n < 2048) ? Whh[(size_t)n * KK + k] : 0.0f;
            g_Wf[nr + k]  = __float2half(acc[r][c] + base);
            g_W0f[nr + k] = __float2half(base);
        }
    }
}

// ---------------------------------------------------------------------------
// Per-m-row barrier: 34 CTAs of one m-row group.
// ---------------------------------------------------------------------------
__device__ __forceinline__ void row_barrier(int mrow, unsigned& phase) {
    __threadfence();
    __syncthreads();
    phase += GROUP;
    if (threadIdx.x == 0) {
        atomicAdd(&g_bar4[mrow * 32], 1u);
        while (*(volatile unsigned*)&g_bar4[mrow * 32] < phase) { }
        __threadfence();
    }
    __syncthreads();
}

// ---------------------------------------------------------------------------
// Persistent rollout. Warp grid 4m x 2n (32x64 warp tiles), gates fully
// register-local (16j interleave). DOUBLE-buffered fp16 h: read buffer t&1,
// write buffer (t+1)&1 — removes the writer/straggler-reader race that
// single-buffered h relied on timing to avoid.
// 3-stage KC=128 pipeline, ONE __syncthreads per chunk:
//   cp_wait(c) -> sync -> issue load(c+2) -> mma(c)
// B chunk 0 of step t+1 prefetched across the barrier (weights static).
// ---------------------------------------------------------------------------
__global__ void __launch_bounds__(TPB, 1)
rollout(float* __restrict__ out, const float* __restrict__ ctx,
        const float* __restrict__ b_head) {
    extern __shared__ __align__(128) char smem[];
    __shared__ float s_b5[128], s_b50[128];
    const uint32_t sm0 = smem_u32(smem);

    const int tid = threadIdx.x;
    const int lane = tid & 31;
    const int wid = tid >> 5;
    const int wm = wid & 3;              // rows 32*wm .. +31
    const int wn = wid >> 2;             // cols 64*wn .. +63
    const int cta = blockIdx.x;
    const int mrow = cta & 3;
    const int m0 = mrow * 128;
    const int nt = cta >> 2;             // 0..33
    const bool is_y = (nt >= 32);

    // Per-CTA bias staging (interleaved col c = 64*(j/16) + 16*g + (j%16)).
    if (tid < 128) {
        if (!is_y) {
            int g = (tid & 63) >> 4;
            int jl = (tid >> 6) * 16 + (tid & 15);
            s_b5[tid]  = g_b5[g * 1024 + 32 * nt + jl];
            s_b50[tid] = g_b50[g * 1024 + 32 * nt + jl];
        } else {
            s_b5[tid] = __ldg(b_head + (nt - 32) * 128 + tid);
        }
    }
    __syncthreads();

    const int jc = 2 * (lane & 3);
    const int rq = lane >> 2;

    // Register-resident fp32 h_old: [mt][rs][h8][e] -> 16 values.
    float ho[16];
    if (!is_y) {
#pragma unroll
        for (int mt = 0; mt < 2; ++mt)
#pragma unroll
            for (int rs = 0; rs < 2; ++rs)
#pragma unroll
                for (int h8 = 0; h8 < 2; ++h8)
#pragma unroll
                    for (int e = 0; e < 2; ++e) {
                        int row = m0 + 32 * wm + 16 * mt + 8 * rs + rq;
                        int j = 32 * nt + 16 * wn + 8 * h8 + jc + e;
                        ho[((mt * 2 + rs) * 2 + h8) * 2 + e] =
                            ctx[(size_t)row * HH + j];
                    }
    }

    const uint32_t lm = (uint32_t)(lane & 15) * ROWB + (uint32_t)(lane >> 4) * 16;

    // Loaders: 2048 16B segments per 128x128 tile -> 8 per thread.
    auto load_B = [&](const fp16* Bw, int kc0, int sbuf) {
        const uint32_t sb = sm0 + sbuf * STAGE_BYTES + BUFB;
#pragma unroll
        for (int p = 0; p < 8; ++p) {
            const int s = tid + 256 * p;
            const int row = s >> 4;
            const int cs = s & 15;
            CP_ASYNC16(sb + (uint32_t)row * ROWB + (uint32_t)cs * 16,
                       Bw + (size_t)row * KK + kc0 + cs * 8);
        }
        CP_COMMIT();
    };
    auto load_A = [&](const fp16* Am, int kc0, int sbuf) {
        const uint32_t sb = sm0 + sbuf * STAGE_BYTES;
#pragma unroll
        for (int p = 0; p < 8; ++p) {
            const int s = tid + 256 * p;
            const int row = s >> 4;
            const int cs = s & 15;
            CP_ASYNC16(sb + (uint32_t)row * ROWB + (uint32_t)cs * 16,
                       Am + (size_t)row * KK + kc0 + cs * 8);
        }
        CP_COMMIT();
    };
    auto load_AB = [&](const fp16* Am, const fp16* Bw, int kc0, int sbuf) {
        const uint32_t sa = sm0 + sbuf * STAGE_BYTES;
#pragma unroll
        for (int p = 0; p < 8; ++p) {
            const int s = tid + 256 * p;
            const int row = s >> 4;
            const int cs = s & 15;
            const uint32_t soff = (uint32_t)row * ROWB + (uint32_t)cs * 16;
            const size_t goff = (size_t)row * KK + kc0 + cs * 8;
            CP_ASYNC16(sa + soff, Am + goff);
            CP_ASYNC16(sa + BUFB + soff, Bw + goff);
        }
        CP_COMMIT();
    };

    unsigned gphase = 0;

    // Pre-loop B prefetch for t=0 (gate CTAs are active at t=0).
    if (!is_y) load_B(g_W0f + (size_t)(nt * 128) * KK, 0, 0);

    for (int t = 0; t <= LL; ++t) {
        const bool active = (t < LL) ? !(t == 0 && is_y) : is_y;
        if (active) {
            const fp16* Bw = ((t == 0) ? g_W0f : g_Wf) + (size_t)(nt * 128) * KK;
            const fp16* Am = g_hb + (size_t)(t & 1) * (BB * HH) + (size_t)m0 * KK;

            float acc[2][8][4];
#pragma unroll
            for (int i = 0; i < 2; ++i)
#pragma unroll
                for (int j = 0; j < 8; ++j)
#pragma unroll
                    for (int k = 0; k < 4; ++k) acc[i][j][k] = 0.0f;

            // Prologue: A chunk 0 (B0 pre-barrier), then chunk 1 full.
            load_A(Am, 0, 0);
            load_AB(Am, Bw, KC, 1);

            for (int c = 0; c < NCHUNK; ++c) {
                const int sbuf = c % 3;
                if (c + 1 < NCHUNK) cp_wait<1>(); else cp_wait<0>();
                // One sync: everyone's chunk-c data visible AND everyone has
                // finished reading chunk c-1's stage (about to be reloaded).
                __syncthreads();
                if (c + 2 < NCHUNK) {
                    int ns = sbuf + 2; if (ns >= NSTG) ns -= NSTG;
                    load_AB(Am, Bw, (c + 2) * KC, ns);
                }

                const uint32_t sb = sm0 + sbuf * STAGE_BYTES;
                const uint32_t abase = sb + (uint32_t)(32 * wm) * ROWB + lm;
                const uint32_t bbase = sb + BUFB + (uint32_t)(64 * wn) * ROWB + lm;
#pragma unroll
                for (int ks = 0; ks < 8; ++ks) {
                    const uint32_t ko = (uint32_t)ks * 32;
                    uint32_t ah0[4], ah1[4];
                    ldsm_x4(ah0, abase + ko);
                    ldsm_x4(ah1, abase + (uint32_t)(16 * ROWB) + ko);
#pragma unroll
                    for (int u = 0; u < 4; ++u) {
                        uint32_t bb[4];
                        ldsm_x4(bb, bbase + (uint32_t)(16 * u) * ROWB + ko);
                        mma_fp16(acc[0][2 * u + 0], ah0, bb[0], bb[2]);
                        mma_fp16(acc[0][2 * u + 1], ah0, bb[1], bb[3]);
                        mma_fp16(acc[1][2 * u + 0], ah1, bb[0], bb[2]);
                        mma_fp16(acc[1][2 * u + 1], ah1, bb[1], bb[3]);
                    }
                }
            }

            // ---- fused epilogue ----
            if (!is_y) {
                fp16* hw = g_hb + (size_t)((t + 1) & 1) * (BB * HH);
                const float* sb2 = (t == 0) ? s_b50 : s_b5;
#pragma unroll
                for (int mt = 0; mt < 2; ++mt)
#pragma unroll
                    for (int rs = 0; rs < 2; ++rs) {
                        const int row = m0 + 32 * wm + 16 * mt + 8 * rs + rq;
#pragma unroll
                        for (int h8 = 0; h8 < 2; ++h8) {
                            float hn[2];
#pragma unroll
                            for (int e = 0; e < 2; ++e) {
                                const int cb = 64 * wn + 8 * h8 + jc + e;
                                float rp = acc[mt][0 + h8][2 * rs + e] + sb2[cb];
                                float zp = acc[mt][2 + h8][2 * rs + e] + sb2[cb + 16];
                                float gn = acc[mt][4 + h8][2 * rs + e] + sb2[cb + 32];
                                float gh = acc[mt][6 + h8][2 * rs + e] + sb2[cb + 48];
                                float r = fsigmoid(rp);
                                float z = fsigmoid(zp);
                                float nn = ftanh(gn + r * gh);
                                const int ii = ((mt * 2 + rs) * 2 + h8) * 2 + e;
                                float hnew = (1.0f - z) * nn + z * ho[ii];
                                ho[ii] = hnew;
                                hn[e] = hnew;
                            }
                            const int jb = 32 * nt + 16 * wn + 8 * h8 + jc;
                            *reinterpret_cast<__half2*>(hw + (size_t)row * HH + jb) =
                                __floats2half2_rn(hn[0], hn[1]);
                        }
                    }
            } else {
                float* yb = out + (size_t)(t - 1) * BB * II;
#pragma unroll
                for (int mt = 0; mt < 2; ++mt)
#pragma unroll
                    for (int rs = 0; rs < 2; ++rs) {
                        const int row = m0 + 32 * wm + 16 * mt + 8 * rs + rq;
#pragma unroll
                        for (int f = 0; f < 8; ++f) {
                            const int ci = 64 * wn + 8 * f + jc;
                            const int col = (nt - 32) * 128 + ci;
                            float2 v = make_float2(acc[mt][f][2 * rs + 0] + s_b5[ci],
                                                   acc[mt][f][2 * rs + 1] + s_b5[ci + 1]);
                            *reinterpret_cast<float2*>(yb + (size_t)row * II + col) = v;
                        }
                    }
            }
        }

        if (t == LL) break;

        // Pre-barrier B prefetch for t+1 (weights static; stage 0's B half
        // was last consumed at chunk 6). Gate CTAs inactive at t+1 == LL.
        const bool next_active = is_y ? true : (t + 1 < LL);
        if (next_active) load_B(g_Wf + (size_t)(nt * 128) * KK, 0, 0);

        row_barrier(mrow, gphase);
    }
}

// ---------------------------------------------------------------------------
// 3 graph nodes: setup_all, wc_gemm, rollout.
// ---------------------------------------------------------------------------
extern "C" void kernel_launch(void* const* d_in, const int* in_sizes, int n_in,
                              void* d_out, int out_size) {
    const float *ctx = nullptr, *Wih = nullptr, *Whh = nullptr,
                *bih = nullptr, *bhh = nullptr, *Whead = nullptr, *bhead = nullptr;
    int b3_seen = 0;
    for (int i = 0; i < n_in; i++) {
        long sz = in_sizes[i];
        const float* p = (const float*)d_in[i];
        if (sz == (long)BB * HH) ctx = p;
        else if (sz == (long)G3 * II) Wih = p;
        else if (sz == (long)G3 * HH) Whh = p;
        else if (sz == (long)G3) { if (b3_seen++ == 0) bih = p; else bhh = p; }
        else if (sz == (long)II * HH) Whead = p;
        else if (sz == (long)II) bhead = p;
    }
    float* out = (float*)d_out;

    cudaFuncSetAttribute(rollout, cudaFuncAttributeMaxDynamicSharedMemorySize, SMEM_DYN);

    setup_all<<<640, 256>>>(ctx, Wih, bih, bhh, bhead, Whh, Whead);
    wc_gemm<<<dim3(KK / 64, G3 / 64), 256>>>(Wih, Whh, Whead);
    rollout<<<NCTAS, TPB, SMEM_DYN>>>(out, ctx, bhead);

    (void)out_size;
    (void)n_in;
}

// round 14
// speedup vs baseline: 1.0377x; 1.0120x over previous
#include <cuda_runtime.h>
#include <cuda_fp16.h>
#include <cstdint>

// Shapes fixed by the reference.
#define BB 512     // batch
#define HH 1024    // hidden
#define II 256     // input / output feature
#define LL 256     // rollout length
#define G3 3072    // 3*HH
#define NG 4096    // gate GEMM output width (4*HH)
#define N5 4352    // NG + II (appended W_head rows -> y)
#define KK 1024    // GEMM K
#define NCTAS 136  // 4 m-rows x 34 n-tiles (128x128)
#define GROUP 34   // CTAs per independent m-row group
#define TPB 256

#define KC 128                   // fp16 K elements per chunk (256 bytes/row)
#define NCHUNK (KK / KC)         // 8
#define ROWB 272                 // padded smem row bytes (256 + 16)
#define BUFB (128 * ROWB)        // 34816 B per 128x128 fp16 tile
#define STAGE_BYTES (2 * BUFB)   // A, B
#define NSTG 3
#define SMEM_DYN (NSTG * STAGE_BYTES)   // 208896 B (< 227 KB limit)

typedef __half fp16;

// ---------------------------------------------------------------------------
// Static device scratch.
// ---------------------------------------------------------------------------
__device__ fp16  g_hb[2 * BB * HH];     // double-buffered fp16 hidden state
__device__ fp16  g_Wf[N5 * KK];         // fp16 weights, 16j-interleaved
__device__ fp16  g_W0f[N5 * KK];        // fp16 step-0 weights, interleaved
__device__ float g_b5[NG];              // biases (gate-major layout)
__device__ float g_b50[NG];
__device__ unsigned g_bar4[4 * 32];     // per-m-row barrier counters

// ---------------------------------------------------------------------------
// PTX helpers (base ISA, valid on compute_103)
// ---------------------------------------------------------------------------
__device__ __forceinline__ uint32_t smem_u32(const void* p) {
    uint32_t a;
    asm("{ .reg .u64 t; cvta.to.shared.u64 t, %1; cvt.u32.u64 %0, t; }" : "=r"(a) : "l"(p));
    return a;
}
__device__ __forceinline__ void ldsm_x4(uint32_t* r, uint32_t addr) {
    asm volatile("ldmatrix.sync.aligned.m8n8.x4.shared.b16 {%0,%1,%2,%3}, [%4];"
                 : "=r"(r[0]), "=r"(r[1]), "=r"(r[2]), "=r"(r[3]) : "r"(addr));
}
__device__ __forceinline__ void mma_fp16(float* d, const uint32_t* a,
                                         uint32_t b0, uint32_t b1) {
    asm volatile(
        "mma.sync.aligned.m16n8k16.row.col.f32.f16.f16.f32 "
        "{%0,%1,%2,%3}, {%4,%5,%6,%7}, {%8,%9}, {%0,%1,%2,%3};"
        : "+f"(d[0]), "+f"(d[1]), "+f"(d[2]), "+f"(d[3])
        : "r"(a[0]), "r"(a[1]), "r"(a[2]), "r"(a[3]), "r"(b0), "r"(b1));
}
#define CP_ASYNC16(smem, gptr) \
    asm volatile("cp.async.cg.shared.global [%0], [%1], 16;" :: "r"(smem), "l"(gptr))
#define CP_COMMIT() asm volatile("cp.async.commit_group;" ::: "memory")
template <int N>
__device__ __forceinline__ void cp_wait() {
    asm volatile("cp.async.wait_group %0;" :: "n"(N) : "memory");
}
__device__ __forceinline__ float fsigmoid(float x) {
    return __fdividef(1.0f, 1.0f + __expf(-x));
}
__device__ __forceinline__ float ftanh(float x) {
    float e = __expf(2.0f * x);
    return 1.0f - __fdividef(2.0f, e + 1.0f);
}
// Interleaved row for gate row (g, j): (j/16)*64 + g*16 + (j%16)
__device__ __forceinline__ int irow(int g, int j) {
    return ((j >> 4) << 6) + (g << 4) + (j & 15);
}

// ---------------------------------------------------------------------------
// Fused setup: h0 (buffer 0), barrier counters, biases (warp-per-j dot),
// static weight rows. Launch: 512 blocks x 256 threads (4096 warps).
// ---------------------------------------------------------------------------
__global__ void setup_all(const float* __restrict__ ctx,
                          const float* __restrict__ Wih,
                          const float* __restrict__ bih,
                          const float* __restrict__ bhh,
                          const float* __restrict__ bhead,
                          const float* __restrict__ Whh,
                          const float* __restrict__ Whead) {
    const int gs = gridDim.x * blockDim.x;
    const int t0 = blockIdx.x * blockDim.x + threadIdx.x;
    const int lane = threadIdx.x & 31;

    for (int i = t0; i < BB * HH; i += gs) g_hb[i] = __float2half(ctx[i]);
    for (int i = t0; i < 4 * 32; i += gs) g_bar4[i] = 0u;

    // Bias: one warp per j (4096 warps == 4096 j's).
    {
        const int j = t0 >> 5;   // global warp id
        if (j < NG) {
            float v0, v1;
            if (j < 2048)      v0 = bih[j] + bhh[j];
            else if (j < G3)   v0 = bih[j];
            else               v0 = bhh[j - 1024];
            if (j < G3) {
                // dot(Wih[j,:], bhead) — coalesced lanes + shfl reduce.
                const float* wr = Wih + (size_t)j * II;
                float d = 0.0f;
#pragma unroll
                for (int u = 0; u < II / 32; ++u)
                    d = fmaf(wr[lane + 32 * u], __ldg(bhead + lane + 32 * u), d);
#pragma unroll
                for (int s = 16; s > 0; s >>= 1)
                    d += __shfl_xor_sync(0xFFFFFFFFu, d, s);
                float bc = bih[j] + d;
                v1 = (j < 2048) ? (bhh[j] + bc) : bc;
            } else {
                v1 = bhh[j - 1024];
            }
            if (lane == 0) {
                g_b50[j] = v0;
                g_b5[j]  = v1;
            }
        }
    }

    // Rows n in [3072, 4352): ghn block (Whh_n) and y block (Whead).
    for (int idx = t0; idx < (N5 - G3) * KK; idx += gs) {
        int o = G3 + (idx >> 10);
        int k = idx & 1023;
        int nrow;
        float v;
        if (o < NG) {
            nrow = irow(3, o - G3);
            v = Whh[(size_t)(o - 1024) * KK + k];
        } else {
            nrow = o;
            v = Whead[(size_t)(o - NG) * KK + k];
        }
        fp16 h = __float2half(v);
        g_Wf[(size_t)nrow * KK + k]  = h;
        g_W0f[(size_t)nrow * KK + k] = h;
    }
}

// Wc = W_ih @ W_head for rows n < 3072; writes fp16 interleaved weights.
// 128x128 block tile, BK=16, 256 threads, 8x8 microtile.
__global__ void __launch_bounds__(256)
wc_gemm(const float* __restrict__ Wih,
        const float* __restrict__ Whh,
        const float* __restrict__ Whead) {
    __shared__ __align__(16) float As[16][132];   // As[i][n]
    __shared__ __align__(16) float Bs[16][132];   // Bs[i][k]
    const int tid = threadIdx.x;
    const int n0 = blockIdx.y * 128;
    const int k0 = blockIdx.x * 128;
    const int ty = tid >> 4, tx = tid & 15;

    float acc[8][8] = {};
    for (int i0 = 0; i0 < II; i0 += 16) {
        // A tile (transpose): Wih[n0+r][i0+ic..+3], 2 passes of 64 rows.
        {
            int r = tid >> 2, ic = (tid & 3) * 4;
#pragma unroll
            for (int p = 0; p < 2; ++p) {
                float4 av = *reinterpret_cast<const float4*>(
                    Wih + (size_t)(n0 + r + 64 * p) * II + i0 + ic);
                As[ic + 0][r + 64 * p] = av.x; As[ic + 1][r + 64 * p] = av.y;
                As[ic + 2][r + 64 * p] = av.z; As[ic + 3][r + 64 * p] = av.w;
            }
        }
        // B tile (direct): Whead[i0+i][k0+kc..+3], 2 passes of 64 cols.
        {
            int i = tid >> 4, kc = (tid & 15) * 4;
#pragma unroll
            for (int p = 0; p < 2; ++p) {
                float4 bv = *reinterpret_cast<const float4*>(
                    Whead + (size_t)(i0 + i) * KK + k0 + kc + 64 * p);
                *reinterpret_cast<float4*>(&Bs[i][kc + 64 * p]) = bv;
            }
        }
        __syncthreads();
#pragma unroll
        for (int i = 0; i < 16; ++i) {
            float a[8], b[8];
#pragma unroll
            for (int u = 0; u < 8; ++u) a[u] = As[i][ty * 8 + u];
#pragma unroll
            for (int u = 0; u < 8; ++u) b[u] = Bs[i][tx * 8 + u];
#pragma unroll
            for (int r = 0; r < 8; ++r)
#pragma unroll
                for (int c = 0; c < 8; ++c) acc[r][c] = fmaf(a[r], b[c], acc[r][c]);
        }
        __syncthreads();
    }
#pragma unroll
    for (int r = 0; r < 8; ++r) {
        int n = n0 + ty * 8 + r;
        size_t nr = (size_t)irow(n >> 10, n & 1023) * KK;
#pragma unroll
        for (int c = 0; c < 8; ++c) {
            int k = k0 + tx * 8 + c;
            float base = (n < 2048) ? Whh[(size_t)n * KK + k] : 0.0f;
            g_Wf[nr + k]  = __float2half(acc[r][c] + base);
            g_W0f[nr + k] = __float2half(base);
        }
    }
}

// ---------------------------------------------------------------------------
// Per-m-row barrier: 34 CTAs of one m-row group.
// ---------------------------------------------------------------------------
__device__ __forceinline__ void row_barrier(int mrow, unsigned& phase) {
    __threadfence();
    __syncthreads();
    phase += GROUP;
    if (threadIdx.x == 0) {
        atomicAdd(&g_bar4[mrow * 32], 1u);
        while (*(volatile unsigned*)&g_bar4[mrow * 32] < phase) { }
        __threadfence();
    }
    __syncthreads();
}

// ---------------------------------------------------------------------------
// Persistent rollout. Warp grid 4m x 2n (32x64 warp tiles), gates fully
// register-local (16j interleave). Double-buffered fp16 h (read t&1, write
// (t+1)&1). 3-stage KC=128 pipeline, one __syncthreads per chunk.
// B chunk 0 of step t+1 prefetched BEFORE the epilogue (safe: the c=7 sync
// guarantees every warp finished chunk 6, the last reader of stage 0's B),
// so the prefetch streams under the gate math and the barrier.
// ---------------------------------------------------------------------------
__global__ void __launch_bounds__(TPB, 1)
rollout(float* __restrict__ out, const float* __restrict__ ctx,
        const float* __restrict__ b_head) {
    extern __shared__ __align__(128) char smem[];
    __shared__ float s_b5[128], s_b50[128];
    const uint32_t sm0 = smem_u32(smem);

    const int tid = threadIdx.x;
    const int lane = tid & 31;
    const int wid = tid >> 5;
    const int wm = wid & 3;              // rows 32*wm .. +31
    const int wn = wid >> 2;             // cols 64*wn .. +63
    const int cta = blockIdx.x;
    const int mrow = cta & 3;
    const int m0 = mrow * 128;
    const int nt = cta >> 2;             // 0..33
    const bool is_y = (nt >= 32);

    // Per-CTA bias staging (interleaved col c = 64*(j/16) + 16*g + (j%16)).
    if (tid < 128) {
        if (!is_y) {
            int g = (tid & 63) >> 4;
            int jl = (tid >> 6) * 16 + (tid & 15);
            s_b5[tid]  = g_b5[g * 1024 + 32 * nt + jl];
            s_b50[tid] = g_b50[g * 1024 + 32 * nt + jl];
        } else {
            s_b5[tid] = __ldg(b_head + (nt - 32) * 128 + tid);
        }
    }
    __syncthreads();

    const int jc = 2 * (lane & 3);
    const int rq = lane >> 2;

    // Register-resident fp32 h_old: [mt][rs][h8][e] -> 16 values.
    float ho[16];
    if (!is_y) {
#pragma unroll
        for (int mt = 0; mt < 2; ++mt)
#pragma unroll
            for (int rs = 0; rs < 2; ++rs)
#pragma unroll
                for (int h8 = 0; h8 < 2; ++h8)
#pragma unroll
                    for (int e = 0; e < 2; ++e) {
                        int row = m0 + 32 * wm + 16 * mt + 8 * rs + rq;
                        int j = 32 * nt + 16 * wn + 8 * h8 + jc + e;
                        ho[((mt * 2 + rs) * 2 + h8) * 2 + e] =
                            ctx[(size_t)row * HH + j];
                    }
    }

    const uint32_t lm = (uint32_t)(lane & 15) * ROWB + (uint32_t)(lane >> 4) * 16;

    // Loaders: 2048 16B segments per 128x128 tile -> 8 per thread.
    auto load_B = [&](const fp16* Bw, int kc0, int sbuf) {
        const uint32_t sb = sm0 + sbuf * STAGE_BYTES + BUFB;
#pragma unroll
        for (int p = 0; p < 8; ++p) {
            const int s = tid + 256 * p;
            const int row = s >> 4;
            const int cs = s & 15;
            CP_ASYNC16(sb + (uint32_t)row * ROWB + (uint32_t)cs * 16,
                       Bw + (size_t)row * KK + kc0 + cs * 8);
        }
        CP_COMMIT();
    };
    auto load_A = [&](const fp16* Am, int kc0, int sbuf) {
        const uint32_t sb = sm0 + sbuf * STAGE_BYTES;
#pragma unroll
        for (int p = 0; p < 8; ++p) {
            const int s = tid + 256 * p;
            const int row = s >> 4;
            const int cs = s & 15;
            CP_ASYNC16(sb + (uint32_t)row * ROWB + (uint32_t)cs * 16,
                       Am + (size_t)row * KK + kc0 + cs * 8);
        }
        CP_COMMIT();
    };
    auto load_AB = [&](const fp16* Am, const fp16* Bw, int kc0, int sbuf) {
        const uint32_t sa = sm0 + sbuf * STAGE_BYTES;
#pragma unroll
        for (int p = 0; p < 8; ++p) {
            const int s = tid + 256 * p;
            const int row = s >> 4;
            const int cs = s & 15;
            const uint32_t soff = (uint32_t)row * ROWB + (uint32_t)cs * 16;
            const size_t goff = (size_t)row * KK + kc0 + cs * 8;
            CP_ASYNC16(sa + soff, Am + goff);
            CP_ASYNC16(sa + BUFB + soff, Bw + goff);
        }
        CP_COMMIT();
    };

    unsigned gphase = 0;

    // Pre-loop B prefetch for t=0 (gate CTAs are active at t=0).
    if (!is_y) load_B(g_W0f + (size_t)(nt * 128) * KK, 0, 0);

    for (int t = 0; t <= LL; ++t) {
        const bool active = (t < LL) ? !(t == 0 && is_y) : is_y;
        if (active) {
            const fp16* Bw = ((t == 0) ? g_W0f : g_Wf) + (size_t)(nt * 128) * KK;
            const fp16* Am = g_hb + (size_t)(t & 1) * (BB * HH) + (size_t)m0 * KK;

            float acc[2][8][4];
#pragma unroll
            for (int i = 0; i < 2; ++i)
#pragma unroll
                for (int j = 0; j < 8; ++j)
#pragma unroll
                    for (int k = 0; k < 4; ++k) acc[i][j][k] = 0.0f;

            // Prologue: A chunk 0 (B0 pre-barrier), then chunk 1 full.
            load_A(Am, 0, 0);
            load_AB(Am, Bw, KC, 1);

            for (int c = 0; c < NCHUNK; ++c) {
                const int sbuf = c % 3;
                if (c + 1 < NCHUNK) cp_wait<1>(); else cp_wait<0>();
                // One sync: everyone's chunk-c data visible AND everyone has
                // finished reading chunk c-1's stage (about to be reloaded).
                __syncthreads();
                if (c + 2 < NCHUNK) {
                    int ns = sbuf + 2; if (ns >= NSTG) ns -= NSTG;
                    load_AB(Am, Bw, (c + 2) * KC, ns);
                }

                const uint32_t sb = sm0 + sbuf * STAGE_BYTES;
                const uint32_t abase = sb + (uint32_t)(32 * wm) * ROWB + lm;
                const uint32_t bbase = sb + BUFB + (uint32_t)(64 * wn) * ROWB + lm;
#pragma unroll
                for (int ks = 0; ks < 8; ++ks) {
                    const uint32_t ko = (uint32_t)ks * 32;
                    uint32_t ah0[4], ah1[4];
                    ldsm_x4(ah0, abase + ko);
                    ldsm_x4(ah1, abase + (uint32_t)(16 * ROWB) + ko);
#pragma unroll
                    for (int u = 0; u < 4; ++u) {
                        uint32_t bb[4];
                        ldsm_x4(bb, bbase + (uint32_t)(16 * u) * ROWB + ko);
                        mma_fp16(acc[0][2 * u + 0], ah0, bb[0], bb[2]);
                        mma_fp16(acc[0][2 * u + 1], ah0, bb[1], bb[3]);
                        mma_fp16(acc[1][2 * u + 0], ah1, bb[0], bb[2]);
                        mma_fp16(acc[1][2 * u + 1], ah1, bb[1], bb[3]);
                    }
                }
            }

            // Prefetch next step's B chunk 0 NOW — overlaps epilogue + barrier.
            // Safe: every warp passed the c=7 sync, so none still reads the
            // stage-0 B half (last consumed at chunk 6).
            if (t < LL) {
                const bool next_active = is_y ? true : (t + 1 < LL);
                if (next_active) load_B(g_Wf + (size_t)(nt * 128) * KK, 0, 0);
            }

            // ---- fused epilogue ----
            if (!is_y) {
                fp16* hw = g_hb + (size_t)((t + 1) & 1) * (BB * HH);
                const float* sb2 = (t == 0) ? s_b50 : s_b5;
#pragma unroll
                for (int mt = 0; mt < 2; ++mt)
#pragma unroll
                    for (int rs = 0; rs < 2; ++rs) {
                        const int row = m0 + 32 * wm + 16 * mt + 8 * rs + rq;
#pragma unroll
                        for (int h8 = 0; h8 < 2; ++h8) {
                            float hn[2];
#pragma unroll
                            for (int e = 0; e < 2; ++e) {
                                const int cb = 64 * wn + 8 * h8 + jc + e;
                                float rp = acc[mt][0 + h8][2 * rs + e] + sb2[cb];
                                float zp = acc[mt][2 + h8][2 * rs + e] + sb2[cb + 16];
                                float gn = acc[mt][4 + h8][2 * rs + e] + sb2[cb + 32];
                                float gh = acc[mt][6 + h8][2 * rs + e] + sb2[cb + 48];
                                float r = fsigmoid(rp);
                                float z = fsigmoid(zp);
                                float nn = ftanh(gn + r * gh);
                                const int ii = ((mt * 2 + rs) * 2 + h8) * 2 + e;
                                float hnew = (1.0f - z) * nn + z * ho[ii];
                                ho[ii] = hnew;
                                hn[e] = hnew;
                            }
                            const int jb = 32 * nt + 16 * wn + 8 * h8 + jc;
                            *reinterpret_cast<__half2*>(hw + (size_t)row * HH + jb) =
                                __floats2half2_rn(hn[0], hn[1]);
                        }
                    }
            } else {
                float* yb = out + (size_t)(t - 1) * BB * II;
#pragma unroll
                for (int mt = 0; mt < 2; ++mt)
#pragma unroll
                    for (int rs = 0; rs < 2; ++rs) {
                        const int row = m0 + 32 * wm + 16 * mt + 8 * rs + rq;
#pragma unroll
                        for (int f = 0; f < 8; ++f) {
                            const int ci = 64 * wn + 8 * f + jc;
                            const int col = (nt - 32) * 128 + ci;
                            float2 v = make_float2(acc[mt][f][2 * rs + 0] + s_b5[ci],
                                                   acc[mt][f][2 * rs + 1] + s_b5[ci + 1]);
                            *reinterpret_cast<float2*>(yb + (size_t)row * II + col) = v;
                        }
                    }
            }
        } else if (t < LL) {
            // Inactive this step but active next (y CTAs at t=0): prefetch.
            if (is_y) load_B(g_Wf + (size_t)(nt * 128) * KK, 0, 0);
        }

        if (t == LL) break;
        row_barrier(mrow, gphase);
    }
}

// ---------------------------------------------------------------------------
// 3 graph nodes: setup_all, wc_gemm, rollout.
// ---------------------------------------------------------------------------
extern "C" void kernel_launch(void* const* d_in, const int* in_sizes, int n_in,
                              void* d_out, int out_size) {
    const float *ctx = nullptr, *Wih = nullptr, *Whh = nullptr,
                *bih = nullptr, *bhh = nullptr, *Whead = nullptr, *bhead = nullptr;
    int b3_seen = 0;
    for (int i = 0; i < n_in; i++) {
        long sz = in_sizes[i];
        const float* p = (const float*)d_in[i];
        if (sz == (long)BB * HH) ctx = p;
        else if (sz == (long)G3 * II) Wih = p;
        else if (sz == (long)G3 * HH) Whh = p;
        else if (sz == (long)G3) { if (b3_seen++ == 0) bih = p; else bhh = p; }
        else if (sz == (long)II * HH) Whead = p;
        else if (sz == (long)II) bhead = p;
    }
    float* out = (float*)d_out;

    cudaFuncSetAttribute(rollout, cudaFuncAttributeMaxDynamicSharedMemorySize, SMEM_DYN);

    setup_all<<<512, 256>>>(ctx, Wih, bih, bhh, bhead, Whh, Whead);
    wc_gemm<<<dim3(KK / 128, G3 / 128), 256>>>(Wih, Whh, Whead);
    rollout<<<NCTAS, TPB, SMEM_DYN>>>(out, ctx, bhead);

    (void)out_size;
    (void)n_in;
}